// round 2
// baseline (speedup 1.0000x reference)
#include <cuda_runtime.h>
#include <math_constants.h>

// Encoder_46806553591978: per-word softmax-attention pooling over subword spans.
// Two-phase (dot pass + blend pass with L1-hot reload) to minimize live
// registers and maximize occupancy; workload is L2-resident (75MB < 126MB L2).

#define D_DIM      768
#define VEC        (D_DIM / 4)      // 192 float4
#define PER_LANE   (VEC / 32)       // 6 float4 per lane
#define WARPS_PB   8
#define THREADS_PB (WARPS_PB * 32)

__global__ __launch_bounds__(THREADS_PB, 4)
void encoder_word_pool_kernel(const float* __restrict__ emb,
                              const int*   __restrict__ offs,
                              const float* __restrict__ attn_w,
                              const float* __restrict__ attn_b,
                              float*       __restrict__ out,
                              int n_words)
{
    __shared__ float4 sw[VEC];

    const int tid = threadIdx.x;
    for (int i = tid; i < VEC; i += THREADS_PB)
        sw[i] = reinterpret_cast<const float4*>(attn_w)[i];
    __syncthreads();

    const int word = blockIdx.x * WARPS_PB + (tid >> 5);
    const int lane = tid & 31;
    if (word >= n_words) return;

    const int start = offs[2 * word];
    const int end   = offs[2 * word + 1];
    const float bias = *attn_b;

    float4* __restrict__ po = reinterpret_cast<float4*>(out + (size_t)word * D_DIM);

    if (end - start == 2) {
        const float4* __restrict__ p0 =
            reinterpret_cast<const float4*>(emb + (size_t)start * D_DIM);
        const float4* __restrict__ p1 = p0 + VEC;   // contiguous next row

        // ---- phase 1: dots only (rows not retained) ----
        float d0 = 0.f, d1 = 0.f;
        #pragma unroll
        for (int k = 0; k < PER_LANE; ++k) {
            const int idx = lane + 32 * k;
            const float4 wv = sw[idx];
            const float4 a  = p0[idx];
            const float4 b  = p1[idx];
            d0 += a.x * wv.x + a.y * wv.y + a.z * wv.z + a.w * wv.w;
            d1 += b.x * wv.x + b.y * wv.y + b.z * wv.z + b.w * wv.w;
        }
        #pragma unroll
        for (int o = 16; o > 0; o >>= 1) {
            d0 += __shfl_xor_sync(0xffffffffu, d0, o);
            d1 += __shfl_xor_sync(0xffffffffu, d1, o);
        }
        d0 += bias; d1 += bias;

        const float m   = fmaxf(d0, d1);
        const float e0  = __expf(d0 - m);
        const float e1  = __expf(d1 - m);
        const float inv = 1.f / (e0 + e1);
        const float a0 = e0 * inv, a1 = e1 * inv;

        // ---- phase 2: reload rows (L1-hot) and blend ----
        #pragma unroll
        for (int k = 0; k < PER_LANE; ++k) {
            const int idx = lane + 32 * k;
            const float4 a = p0[idx];
            const float4 b = p1[idx];
            float4 o4;
            o4.x = a0 * a.x + a1 * b.x;
            o4.y = a0 * a.y + a1 * b.y;
            o4.z = a0 * a.z + a1 * b.z;
            o4.w = a0 * a.w + a1 * b.w;
            po[idx] = o4;
        }
    } else {
        // ---- generic span, two-pass online softmax ----
        // Pass A: streaming max + denom (no row retention).
        float m = -CUDART_INF_F;
        float denom = 0.f;
        for (int s = start; s < end; ++s) {
            const float4* __restrict__ p =
                reinterpret_cast<const float4*>(emb + (size_t)s * D_DIM);
            float d = 0.f;
            #pragma unroll
            for (int k = 0; k < PER_LANE; ++k) {
                const int idx = lane + 32 * k;
                const float4 wv = sw[idx];
                const float4 r  = p[idx];
                d += r.x * wv.x + r.y * wv.y + r.z * wv.z + r.w * wv.w;
            }
            #pragma unroll
            for (int o = 16; o > 0; o >>= 1)
                d += __shfl_xor_sync(0xffffffffu, d, o);
            d += bias;
            const float mn = fmaxf(m, d);
            denom = denom * __expf(m - mn) + __expf(d - mn);
            m = mn;
        }
        const float inv = 1.f / denom;

        // Pass B: recompute each row's dot (L1/L2-hot), accumulate output.
        float acc[PER_LANE * 4];
        #pragma unroll
        for (int k = 0; k < PER_LANE * 4; ++k) acc[k] = 0.f;

        for (int s = start; s < end; ++s) {
            const float4* __restrict__ p =
                reinterpret_cast<const float4*>(emb + (size_t)s * D_DIM);
            float d = 0.f;
            #pragma unroll
            for (int k = 0; k < PER_LANE; ++k) {
                const int idx = lane + 32 * k;
                const float4 wv = sw[idx];
                const float4 r  = p[idx];
                d += r.x * wv.x + r.y * wv.y + r.z * wv.z + r.w * wv.w;
            }
            #pragma unroll
            for (int o = 16; o > 0; o >>= 1)
                d += __shfl_xor_sync(0xffffffffu, d, o);
            d += bias;
            const float w8 = __expf(d - m) * inv;
            #pragma unroll
            for (int k = 0; k < PER_LANE; ++k) {
                const int idx = lane + 32 * k;
                const float4 r = p[idx];
                acc[4*k+0] += w8 * r.x;
                acc[4*k+1] += w8 * r.y;
                acc[4*k+2] += w8 * r.z;
                acc[4*k+3] += w8 * r.w;
            }
        }
        #pragma unroll
        for (int k = 0; k < PER_LANE; ++k) {
            float4 o4;
            o4.x = acc[4*k+0];
            o4.y = acc[4*k+1];
            o4.z = acc[4*k+2];
            o4.w = acc[4*k+3];
            po[lane + 32 * k] = o4;
        }
    }
}

extern "C" void kernel_launch(void* const* d_in, const int* in_sizes, int n_in,
                              void* d_out, int out_size)
{
    const float* emb    = (const float*)d_in[0];   // [n_subwords, 768] fp32
    const int*   offs   = (const int*)  d_in[1];   // [n_words, 2] int32
    const float* attn_w = (const float*)d_in[2];   // [768] fp32
    const float* attn_b = (const float*)d_in[3];   // scalar fp32
    float*       out    = (float*)d_out;           // [n_words, 768] fp32

    const int n_words = in_sizes[1] / 2;
    const int blocks  = (n_words + WARPS_PB - 1) / WARPS_PB;

    encoder_word_pool_kernel<<<blocks, THREADS_PB>>>(emb, offs, attn_w, attn_b,
                                                     out, n_words);
}